// round 14
// baseline (speedup 1.0000x reference)
#include <cuda_runtime.h>
#include <cuda_fp16.h>
#include <cuda_bf16.h>
#include <math.h>

#define NN      20000
#define NNP     20480        // padded for csr_scan vector path
#define NE      500000
#define NGR     64
#define NGAUSS  100
#define NLAYER  6
#define FCW     128
#define EMBW    92

#define DELTA     (6.0f/99.0f)
#define INV_DELTA (99.0f/6.0f)
#define COEFF     (-0.5f/(DELTA*DELTA))

// nearest-neighbor distance table: h = DELTA/256
#define MT2       25346
#define T2_INVH   4224.0f    // 99*256/6
#define T2_H      (1.0f/4224.0f)

// BN statistics subsampling
#define SUB       8
#define NSAMP     (NE/SUB)   // 62500

#define TAB_BLOCKS 100       // blocks per layer for build_tables
#define TAB_SMEM   ((NGAUSS*128 + 128)*4)
#define GEMM_BLOCKS ((NN + 63)/64)   // 313

// smem strides (halves) padded for conflict-free ldmatrix
#define A_LD  72
#define B_LD  264

// ---------------- scratch (device globals; no allocs allowed) ----------------
__device__ float  g_x[NN*64];
__device__ __nv_bfloat16 g_xh[NN*64];     // bf16 copy of x for tensor-core gemm
__device__ __half g_Ph[NN*128];           // P = x@W1, permuted, fp16
__device__ __half g_Qh[NN*128];           // Q = x@W2, permuted, fp16
__device__ __half g_Th6[NLAYER*MT2*128];  // all 6 layers' ef@W3+b tables, permuted fp16
__device__ int    g_deg[NNP];
__device__ int    g_rowstart[NNP+1];
__device__ int    g_cursor[NNP];
__device__ unsigned int g_pack[NE];       // src (15b) | m (<<15), CSR order
__device__ double g_bn_sum[NLAYER*128];
__device__ double g_bn_ssq[NLAYER*128];
__device__ float  g_mol[NGR*64];
__device__ float  g_cnt[NGR];

// ---------------- helpers ----------------
__device__ __forceinline__ float splusf(float x){
    float e = __expf(-fabsf(x));
    return fmaxf(x, 0.0f) + __logf(1.0f + e);
}
// softplus with ONE MUFU: u=e^{-|x|}; ln(1+u) = deg-8 poly in t=2u-1 (abs err <1e-5)
__device__ __forceinline__ float splus_p(float x){
    float u = __expf(-fabsf(x));
    float t = fmaf(2.0f, u, -1.0f);
    float p =              -1.90519e-5f;
    p = fmaf(p, t,  6.53210e-5f);
    p = fmaf(p, t, -2.2862826e-4f);
    p = fmaf(p, t,  8.2304527e-4f);
    p = fmaf(p, t, -3.0864198e-3f);
    p = fmaf(p, t,  1.2345679e-2f);
    p = fmaf(p, t, -5.5555556e-2f);
    p = fmaf(p, t,  3.3333333e-1f);
    p = fmaf(p, t,  4.0546511e-1f);
    return fmaxf(x, 0.0f) + p;
}
// two sigmoids with ONE MUFU: tanh.approx.f16x2
__device__ __forceinline__ float2 sigm2(float z0, float z1){
    __half2 h = __floats2half2_rn(0.5f*z0, 0.5f*z1);
    unsigned hu = *reinterpret_cast<unsigned*>(&h);
    unsigned r;
    asm("tanh.approx.f16x2 %0, %1;" : "=r"(r) : "r"(hu));
    __half2 rh = *reinterpret_cast<__half2*>(&r);
    float2 f = __half22float2(rh);
    return make_float2(fmaf(0.5f, f.x, 0.5f), fmaf(0.5f, f.y, 0.5f));
}
// channel c (0..127) -> permuted position: lane L holds {2L,2L+1,2L+64,2L+65}
__device__ __forceinline__ int chpos(int c){
    return ((c & 63) >> 1)*4 + ((c >> 6) << 1) + (c & 1);
}
__device__ __forceinline__ void ld_h4(const __half* p, float& a, float& b, float& c, float& d){
    uint2 u = *reinterpret_cast<const uint2*>(p);
    float2 f0 = __half22float2(*reinterpret_cast<__half2*>(&u.x));
    float2 f1 = __half22float2(*reinterpret_cast<__half2*>(&u.y));
    a = f0.x; b = f0.y; c = f1.x; d = f1.y;
}
// load q row + t row, add in half2, return 4 floats
__device__ __forceinline__ void qt_add4(const __half* q, const __half* t,
                                        float& a, float& b, float& c, float& d){
    uint2 uq = *reinterpret_cast<const uint2*>(q);
    uint2 ut = *reinterpret_cast<const uint2*>(t);
    __half2 s01 = __hadd2(*reinterpret_cast<__half2*>(&uq.x), *reinterpret_cast<__half2*>(&ut.x));
    __half2 s23 = __hadd2(*reinterpret_cast<__half2*>(&uq.y), *reinterpret_cast<__half2*>(&ut.y));
    float2 f0 = __half22float2(s01);
    float2 f1 = __half22float2(s23);
    a = f0.x; b = f0.y; c = f1.x; d = f1.y;
}

// ---------------- x = embedding[an] @ nuc_W + nuc_b ----------------
__global__ void nuc_kernel(const int* __restrict__ an, const float* __restrict__ emb,
                           const float* __restrict__ W, const float* __restrict__ b){
    __shared__ float Ws[EMBW*64];
    __shared__ float bs[64];
    for (int i = threadIdx.x; i < EMBW*64; i += blockDim.x) Ws[i] = W[i];
    if (threadIdx.x < 64) bs[threadIdx.x] = b[threadIdx.x];
    __syncthreads();
    int lane = threadIdx.x & 31;
    int warp = (blockIdx.x*blockDim.x + threadIdx.x) >> 5;
    int nw   = (gridDim.x*blockDim.x) >> 5;
    for (int n = warp; n < NN; n += nw){
        const float* er = emb + an[n]*EMBW;
        float a0 = bs[lane], a1 = bs[lane+32];
        #pragma unroll 4
        for (int e = 0; e < EMBW; e++){
            float v = __ldg(er + e);
            a0 = fmaf(v, Ws[e*64 + lane],      a0);
            a1 = fmaf(v, Ws[e*64 + lane + 32], a1);
        }
        g_x[n*64 + lane]       = a0;
        g_x[n*64 + lane + 32]  = a1;
        g_xh[n*64 + lane]      = __float2bfloat16(a0);
        g_xh[n*64 + lane + 32] = __float2bfloat16(a1);
    }
}

// ---------------- one-time zeroing ----------------
__global__ void csr_zero(){
    int i = blockIdx.x*blockDim.x + threadIdx.x;
    if (i < NNP) g_deg[i] = 0;
    if (i < NGR*64) g_mol[i] = 0.0f;
    if (i < NGR)    g_cnt[i] = 0.0f;
    if (i < NLAYER*128){ g_bn_sum[i] = 0.0; g_bn_ssq[i] = 0.0; }
}
__global__ void csr_hist(const int* __restrict__ nbr){
    int i = blockIdx.x*blockDim.x + threadIdx.x;
    int stride = gridDim.x*blockDim.x;
    for (int e = i; e < NE; e += stride)
        atomicAdd(&g_deg[__ldg(nbr + NE + e)], 1);
}
__global__ void csr_scan(){   // single block, 1024 threads, 20 items each (padded)
    __shared__ int wsum[32];
    int t = threadIdx.x, lane = t & 31, wid = t >> 5;
    int base = t*20;
    int4 v[5];
    int loc = 0;
    #pragma unroll
    for (int j = 0; j < 5; j++){
        v[j] = *reinterpret_cast<const int4*>(g_deg + base + j*4);
        loc += v[j].x + v[j].y + v[j].z + v[j].w;
    }
    int sc = loc;
    #pragma unroll
    for (int off = 1; off < 32; off <<= 1){
        int u = __shfl_up_sync(0xffffffffu, sc, off);
        if (lane >= off) sc += u;
    }
    if (lane == 31) wsum[wid] = sc;
    __syncthreads();
    if (wid == 0){
        int w = wsum[lane];
        #pragma unroll
        for (int off = 1; off < 32; off <<= 1){
            int u = __shfl_up_sync(0xffffffffu, w, off);
            if (lane >= off) w += u;
        }
        wsum[lane] = w;
    }
    __syncthreads();
    int run = sc - loc + (wid ? wsum[wid-1] : 0);
    #pragma unroll
    for (int j = 0; j < 5; j++){
        int4 rs;
        rs.x = run; run += v[j].x;
        rs.y = run; run += v[j].y;
        rs.z = run; run += v[j].z;
        rs.w = run; run += v[j].w;
        *reinterpret_cast<int4*>(g_rowstart + base + j*4) = rs;
        *reinterpret_cast<int4*>(g_cursor   + base + j*4) = rs;
    }
    if (t == 1023) g_rowstart[NNP] = wsum[31];
}
__global__ void csr_scatter(const int* __restrict__ nbr, const float* __restrict__ dist){
    int i = blockIdx.x*blockDim.x + threadIdx.x;
    int stride = gridDim.x*blockDim.x;
    for (int e = i; e < NE; e += stride){
        int dn = __ldg(nbr + NE + e);
        int sn = __ldg(nbr + e);
        float d = __ldg(dist + e);
        int m = min(__float2int_rn(d * T2_INVH), MT2 - 1);
        int pos = atomicAdd(&g_cursor[dn], 1);
        g_pack[pos] = (unsigned)sn | ((unsigned)m << 15);
    }
}

// ---- build ALL 6 tables up front, warp-autonomous (no per-row barriers) ----
__global__ void build_tables(const float* __restrict__ convW, const float* __restrict__ convb){
    extern __shared__ float sm[];
    float* W3s = sm;                 // [100][128]
    float* bs  = sm + NGAUSS*128;    // [128]
    int layer = blockIdx.x / TAB_BLOCKS;
    int tb    = blockIdx.x % TAB_BLOCKS;
    const float* W3 = convW + layer*228*128 + 128*128;
    const float* bl = convb + layer*128;
    __half* Tl = g_Th6 + (size_t)layer*MT2*128;
    for (int i = threadIdx.x; i < NGAUSS*128; i += blockDim.x) W3s[i] = W3[i];
    if (threadIdx.x < 128) bs[threadIdx.x] = bl[threadIdx.x];
    __syncthreads();
    int lane = threadIdx.x & 31;
    int wid  = threadIdx.x >> 5;     // 8 warps per block
    int c0 = lane*4;                 // this lane's 4 channels
    int p0 = chpos(c0), p1 = chpos(c0+1), p2 = chpos(c0+2), p3 = chpos(c0+3);
    float b0 = bs[c0], b1 = bs[c0+1], b2 = bs[c0+2], b3 = bs[c0+3];
    int per = (MT2 + TAB_BLOCKS - 1) / TAB_BLOCKS;
    int m0 = tb*per;
    int m1 = min(m0 + per, MT2);
    for (int m = m0 + wid; m < m1; m += 8){
        float d = (float)m * T2_H;
        int kc = __float2int_rn(d * INV_DELTA);
        int k0 = max(kc - 8, 0);
        int k1 = min(kc + 8, NGAUSS - 1);
        int cnt = k1 - k0 + 1;
        float myw = 0.0f;
        if (lane < cnt){ float t = d - (float)(k0+lane)*DELTA; myw = __expf(COEFF*t*t); }
        float a0 = b0, a1 = b1, a2 = b2, a3 = b3;
        for (int k = 0; k < cnt; k++){
            float w = __shfl_sync(0xffffffffu, myw, k);
            float4 wr = *reinterpret_cast<const float4*>(W3s + (k0+k)*128 + c0);
            a0 = fmaf(w, wr.x, a0);
            a1 = fmaf(w, wr.y, a1);
            a2 = fmaf(w, wr.z, a2);
            a3 = fmaf(w, wr.w, a3);
        }
        __half* out = Tl + (size_t)m*128;
        out[p0] = __float2half_rn(a0);
        out[p1] = __float2half_rn(a1);
        out[p2] = __float2half_rn(a2);
        out[p3] = __float2half_rn(a3);
    }
}

// ---------------- P/Q gemm via tensor cores (mma.sync bf16, fp32 accum) --------
__global__ void gemm_mma(const float* __restrict__ Wl){
    __shared__ __nv_bfloat16 As[64*A_LD];
    __shared__ __nv_bfloat16 Bs[64*B_LD];
    int tid = threadIdx.x;
    int n0 = blockIdx.x * 64;
    for (int i = tid; i < 64*256; i += 256){
        int k = i >> 8, n = i & 255;
        float w = (n < 128) ? __ldg(Wl + k*128 + n) : __ldg(Wl + (64+k)*128 + (n-128));
        Bs[k*B_LD + n] = __float2bfloat16(w);
    }
    for (int i = tid; i < 64*64; i += 256){
        int r = i >> 6, k = i & 63;
        int node = n0 + r;
        As[r*A_LD + k] = (node < NN) ? g_xh[node*64 + k] : __float2bfloat16(0.0f);
    }
    __syncthreads();
    int lane = tid & 31, wid = tid >> 5;
    int wm = (wid >> 2) * 32;
    int wn = (wid & 3) * 64;
    float acc[2][8][4];
    #pragma unroll
    for (int mt = 0; mt < 2; mt++)
        #pragma unroll
        for (int nt = 0; nt < 8; nt++)
            #pragma unroll
            for (int q = 0; q < 4; q++) acc[mt][nt][q] = 0.0f;

    int ar = lane & 15;
    int ac = (lane >> 4) * 8;
    int bk = lane & 7;
    int bh = (lane >> 3) & 1;
    #pragma unroll
    for (int ks = 0; ks < 4; ks++){
        unsigned a[2][4];
        #pragma unroll
        for (int mt = 0; mt < 2; mt++){
            unsigned sa = (unsigned)__cvta_generic_to_shared(
                As + (wm + mt*16 + ar)*A_LD + ks*16 + ac);
            asm volatile("ldmatrix.sync.aligned.m8n8.x4.shared.b16 {%0,%1,%2,%3}, [%4];"
                : "=r"(a[mt][0]), "=r"(a[mt][1]), "=r"(a[mt][2]), "=r"(a[mt][3]) : "r"(sa));
        }
        unsigned b[8][2];
        #pragma unroll
        for (int nt = 0; nt < 8; nt++){
            unsigned sb = (unsigned)__cvta_generic_to_shared(
                Bs + (ks*16 + bh*8 + bk)*B_LD + wn + nt*8);
            asm volatile("ldmatrix.sync.aligned.m8n8.x2.trans.shared.b16 {%0,%1}, [%2];"
                : "=r"(b[nt][0]), "=r"(b[nt][1]) : "r"(sb));
        }
        #pragma unroll
        for (int mt = 0; mt < 2; mt++)
            #pragma unroll
            for (int nt = 0; nt < 8; nt++){
                asm volatile(
                    "mma.sync.aligned.m16n8k16.row.col.f32.bf16.bf16.f32 "
                    "{%0,%1,%2,%3}, {%4,%5,%6,%7}, {%8,%9}, {%0,%1,%2,%3};"
                    : "+f"(acc[mt][nt][0]), "+f"(acc[mt][nt][1]),
                      "+f"(acc[mt][nt][2]), "+f"(acc[mt][nt][3])
                    : "r"(a[mt][0]), "r"(a[mt][1]), "r"(a[mt][2]), "r"(a[mt][3]),
                      "r"(b[nt][0]), "r"(b[nt][1]));
            }
    }
    #pragma unroll
    for (int mt = 0; mt < 2; mt++)
        #pragma unroll
        for (int nt = 0; nt < 8; nt++){
            int col = wn + nt*8 + (lane & 3)*2;
            __half* dst; int cp;
            if (col < 128){ dst = g_Ph; cp = chpos(col); }
            else          { dst = g_Qh; cp = chpos(col - 128); }
            int r0 = n0 + wm + mt*16 + (lane >> 2);
            if (r0 < NN){
                dst[r0*128 + cp]     = __float2half_rn(acc[mt][nt][0]);
                dst[r0*128 + cp + 1] = __float2half_rn(acc[mt][nt][1]);
            }
            int r1 = r0 + 8;
            if (r1 < NN){
                dst[r1*128 + cp]     = __float2half_rn(acc[mt][nt][2]);
                dst[r1*128 + cp + 1] = __float2half_rn(acc[mt][nt][3]);
            }
        }
}

// ---- BN stats over every SUB-th edge, edge-centric flat loop ----
__global__ void bn_pass(const int* __restrict__ nbr, const float* __restrict__ dist, int layer){
    __shared__ float s_sum[128];
    __shared__ float s_ssq[128];
    if (threadIdx.x < 128){ s_sum[threadIdx.x] = 0.0f; s_ssq[threadIdx.x] = 0.0f; }
    __syncthreads();
    const __half* Tl = g_Th6 + (size_t)layer*MT2*128;
    int lane = threadIdx.x & 31;
    int warp = (blockIdx.x*blockDim.x + threadIdx.x) >> 5;
    int nw   = (gridDim.x*blockDim.x) >> 5;
    float s0=0,s1=0,s2=0,s3=0, q0=0,q1=0,q2=0,q3=0;
    for (int s = warp; s < NSAMP; s += nw){
        int e = s * SUB;
        int dn = __ldg(nbr + NE + e);
        int sn = __ldg(nbr + e);
        float d = __ldg(dist + e);
        int m = min(__float2int_rn(d * T2_INVH), MT2 - 1);
        float p0,p1,p2,p3, a0,a1,a2,a3;
        ld_h4(g_Ph + dn*128 + lane*4, p0,p1,p2,p3);
        qt_add4(g_Qh + sn*128 + lane*4, Tl + (size_t)m*128 + lane*4, a0,a1,a2,a3);
        float z0 = p0+a0, z1 = p1+a1, z2 = p2+a2, z3 = p3+a3;
        s0 += z0; s1 += z1; s2 += z2; s3 += z3;
        q0 = fmaf(z0,z0,q0); q1 = fmaf(z1,z1,q1);
        q2 = fmaf(z2,z2,q2); q3 = fmaf(z3,z3,q3);
    }
    int c = lane*4;   // pos-space
    atomicAdd(&s_sum[c+0],s0); atomicAdd(&s_sum[c+1],s1); atomicAdd(&s_sum[c+2],s2); atomicAdd(&s_sum[c+3],s3);
    atomicAdd(&s_ssq[c+0],q0); atomicAdd(&s_ssq[c+1],q1); atomicAdd(&s_ssq[c+2],q2); atomicAdd(&s_ssq[c+3],q3);
    __syncthreads();
    if (threadIdx.x < 128){
        atomicAdd(&g_bn_sum[layer*128 + threadIdx.x], (double)s_sum[threadIdx.x]);
        atomicAdd(&g_bn_ssq[layer*128 + threadIdx.x], (double)s_ssq[threadIdx.x]);
    }
}

// ---- pass2 (warp per node): BN finalize inline, recompute z, act, agg, LN, residual ----
__global__ void edge_pass2(const float* __restrict__ lng, const float* __restrict__ lnb,
                           const float* __restrict__ bg,  const float* __restrict__ bb,
                           int layer, const int* __restrict__ batch, int do_pool){
    __shared__ __align__(16) float s_ss[256];    // scale[128] | shift[128] (pos-space)
    {
        int t = threadIdx.x;
        if (t < 128){
            int c = 2*(t >> 2) + (t & 1) + (((t >> 1) & 1) << 6);   // inverse perm
            double mu  = g_bn_sum[layer*128 + t] * (1.0/NSAMP);
            double var = g_bn_ssq[layer*128 + t] * (1.0/NSAMP) - mu*mu;
            double inv = 1.0 / sqrt(var + 1e-5);
            double sc  = (double)__ldg(bg + c) * inv;
            s_ss[t]       = (float)sc;
            s_ss[128 + t] = (float)((double)__ldg(bb + c) - mu*sc);
        }
    }
    __syncthreads();
    const __half* Tl = g_Th6 + (size_t)layer*MT2*128;
    int lane = threadIdx.x & 31;
    int warp = (blockIdx.x*blockDim.x + threadIdx.x) >> 5;
    int nw   = (gridDim.x*blockDim.x) >> 5;
    float4 sc = *reinterpret_cast<const float4*>(s_ss + lane*4);
    float4 sh = *reinterpret_cast<const float4*>(s_ss + 128 + lane*4);
    float2 lg = *reinterpret_cast<const float2*>(lng + 2*lane);
    float2 lb = *reinterpret_cast<const float2*>(lnb + 2*lane);
    for (int n = warp; n < NN; n += nw){
        int i0 = g_rowstart[n], i1 = g_rowstart[n+1];
        float p0,p1,p2,p3;
        ld_h4(g_Ph + n*128 + lane*4, p0,p1,p2,p3);
        float ph0 = fmaf(p0, sc.x, sh.x);
        float ph1 = fmaf(p1, sc.y, sh.y);
        float ph2 = fmaf(p2, sc.z, sh.z);
        float ph3 = fmaf(p3, sc.w, sh.w);
        float a0 = 0.0f, a1 = 0.0f;
        for (int base = i0; base < i1; base += 32){
            int cnt = min(32, i1 - base);
            unsigned myv = 0;
            if (base + lane < i1) myv = __ldg(&g_pack[base + lane]);
            int e = 0;
            for (; e + 2 <= cnt; e += 2){
                unsigned va = __shfl_sync(0xffffffffu, myv, e);
                unsigned vb = __shfl_sync(0xffffffffu, myv, e+1);
                float A0,A1,A2,A3, B0,B1,B2,B3;
                qt_add4(g_Qh + (va & 0x7FFFu)*128 + lane*4,
                        Tl + (size_t)(va >> 15)*128 + lane*4, A0,A1,A2,A3);
                qt_add4(g_Qh + (vb & 0x7FFFu)*128 + lane*4,
                        Tl + (size_t)(vb >> 15)*128 + lane*4, B0,B1,B2,B3);
                {
                    float z0 = fmaf(A0, sc.x, ph0);
                    float z1 = fmaf(A1, sc.y, ph1);
                    float z2 = fmaf(A2, sc.z, ph2);
                    float z3 = fmaf(A3, sc.w, ph3);
                    float2 sg = sigm2(z0, z1);
                    a0 = fmaf(sg.x, splus_p(z2), a0);
                    a1 = fmaf(sg.y, splus_p(z3), a1);
                }
                {
                    float z0 = fmaf(B0, sc.x, ph0);
                    float z1 = fmaf(B1, sc.y, ph1);
                    float z2 = fmaf(B2, sc.z, ph2);
                    float z3 = fmaf(B3, sc.w, ph3);
                    float2 sg = sigm2(z0, z1);
                    a0 = fmaf(sg.x, splus_p(z2), a0);
                    a1 = fmaf(sg.y, splus_p(z3), a1);
                }
            }
            if (e < cnt){
                unsigned va = __shfl_sync(0xffffffffu, myv, e);
                float A0,A1,A2,A3;
                qt_add4(g_Qh + (va & 0x7FFFu)*128 + lane*4,
                        Tl + (size_t)(va >> 15)*128 + lane*4, A0,A1,A2,A3);
                float z0 = fmaf(A0, sc.x, ph0);
                float z1 = fmaf(A1, sc.y, ph1);
                float z2 = fmaf(A2, sc.z, ph2);
                float z3 = fmaf(A3, sc.w, ph3);
                float2 sg = sigm2(z0, z1);
                a0 = fmaf(sg.x, splus_p(z2), a0);
                a1 = fmaf(sg.y, splus_p(z3), a1);
            }
        }
        // LayerNorm over 64 channels (2 per lane: ch 2L, 2L+1)
        float s = a0 + a1;
        #pragma unroll
        for (int o = 16; o > 0; o >>= 1) s += __shfl_xor_sync(0xffffffffu, s, o);
        float mu = s * (1.0f/64.0f);
        float d0 = a0 - mu, d1 = a1 - mu;
        float vv = d0*d0 + d1*d1;
        #pragma unroll
        for (int o = 16; o > 0; o >>= 1) vv += __shfl_xor_sync(0xffffffffu, vv, o);
        float inv = rsqrtf(vv * (1.0f/64.0f) + 1e-5f);
        float2 x = *reinterpret_cast<const float2*>(g_x + n*64 + 2*lane);
        float h0 = fmaf(d0*inv, lg.x, lb.x) + x.x;
        float h1 = fmaf(d1*inv, lg.y, lb.y) + x.y;
        float xr0 = splusf(h0), xr1 = splusf(h1);
        if (do_pool){
            int g = __ldg(batch + n);
            atomicAdd(&g_mol[g*64 + 2*lane],     xr0);
            atomicAdd(&g_mol[g*64 + 2*lane + 1], xr1);
            if (lane == 0) atomicAdd(&g_cnt[g], 1.0f);
        } else {
            *reinterpret_cast<float2*>(g_x + n*64 + 2*lane) = make_float2(xr0, xr1);
            g_xh[n*64 + 2*lane]     = __float2bfloat16(xr0);
            g_xh[n*64 + 2*lane + 1] = __float2bfloat16(xr1);
        }
    }
}

// ---------------- fused MLP head ----------------
__global__ void mlp_all(const float* __restrict__ fc1W, const float* __restrict__ fc1b,
                        const float* __restrict__ fcsW, const float* __restrict__ fcsb,
                        const float* __restrict__ outW, const float* __restrict__ outb,
                        float* __restrict__ out){
    __shared__ float buf[2][FCW];
    __shared__ float red[FCW];
    int g = blockIdx.x, j = threadIdx.x;   // 128 threads
    if (j < 64){
        float c = fmaxf(g_cnt[g], 1.0f);
        buf[0][j] = g_mol[g*64 + j] / c;
    }
    __syncthreads();
    float acc = fc1b[j];
    #pragma unroll 4
    for (int f = 0; f < 64; f++) acc = fmaf(buf[0][f], __ldg(fc1W + f*FCW + j), acc);
    buf[1][j] = splusf(acc);
    __syncthreads();
    int cur = 1;
    for (int l = 0; l < 3; l++){
        const float* W = fcsW + l*FCW*FCW;
        float a = fcsb[l*FCW + j];
        #pragma unroll 4
        for (int f = 0; f < FCW; f++) a = fmaf(buf[cur][f], __ldg(W + f*FCW + j), a);
        buf[cur ^ 1][j] = splusf(a);
        cur ^= 1;
        __syncthreads();
    }
    red[j] = buf[cur][j] * __ldg(outW + j);
    __syncthreads();
    for (int o = 64; o > 0; o >>= 1){
        if (j < o) red[j] += red[j + o];
        __syncthreads();
    }
    if (j == 0) out[g] = red[0] + outb[0];
}

// ---------------- launch ----------------
extern "C" void kernel_launch(void* const* d_in, const int* in_sizes, int n_in,
                              void* d_out, int out_size){
    const int*   an    = (const int*)  d_in[0];
    const int*   nbr   = (const int*)  d_in[1];
    const float* dist  = (const float*)d_in[2];
    const int*   batch = (const int*)  d_in[3];
    const float* emb   = (const float*)d_in[4];
    const float* nucW  = (const float*)d_in[5];
    const float* nucb  = (const float*)d_in[6];
    const float* convW = (const float*)d_in[7];
    const float* convb = (const float*)d_in[8];
    const float* bng   = (const float*)d_in[9];
    const float* bnb   = (const float*)d_in[10];
    const float* lng   = (const float*)d_in[11];
    const float* lnb   = (const float*)d_in[12];
    const float* fc1W  = (const float*)d_in[13];
    const float* fc1b  = (const float*)d_in[14];
    const float* fcsW  = (const float*)d_in[15];
    const float* fcsb  = (const float*)d_in[16];
    const float* outW  = (const float*)d_in[17];
    const float* outb  = (const float*)d_in[18];
    float* y = (float*)d_out;

    static cudaStream_t sA = 0, sB = 0;
    static cudaEvent_t  evR = 0, evA = 0, evB = 0;
    if (sA == 0){
        cudaStreamCreateWithFlags(&sA, cudaStreamNonBlocking);
        cudaStreamCreateWithFlags(&sB, cudaStreamNonBlocking);
        cudaEventCreateWithFlags(&evR, cudaEventDisableTiming);
        cudaEventCreateWithFlags(&evA, cudaEventDisableTiming);
        cudaEventCreateWithFlags(&evB, cudaEventDisableTiming);
    }

    cudaFuncSetAttribute(build_tables, cudaFuncAttributeMaxDynamicSharedMemorySize, TAB_SMEM);

    // ---- forked setup: tables (sA) || nuc (sB) || csr chain (legacy) ----
    cudaEventRecord(evR, 0);
    cudaStreamWaitEvent(sA, evR, 0);
    cudaStreamWaitEvent(sB, evR, 0);

    build_tables<<<NLAYER*TAB_BLOCKS, 256, TAB_SMEM, sA>>>(convW, convb);
    nuc_kernel<<<640, 256, 0, sB>>>(an, emb, nucW, nucb);

    csr_zero<<<80, 256>>>();
    csr_hist<<<640, 256>>>(nbr);
    csr_scan<<<1, 1024>>>();
    csr_scatter<<<640, 256>>>(nbr, dist);

    cudaEventRecord(evA, sA);
    cudaEventRecord(evB, sB);
    cudaStreamWaitEvent(0, evA, 0);
    cudaStreamWaitEvent(0, evB, 0);

    // ---- per-layer pipeline (legacy stream, serial by dependency) ----
    for (int l = 0; l < NLAYER; l++){
        gemm_mma<<<GEMM_BLOCKS, 256>>>(convW + l*228*128);
        bn_pass<<<592, 256>>>(nbr, dist, l);
        edge_pass2<<<640, 256>>>(lng + l*64, lnb + l*64, bng + l*128, bnb + l*128,
                                 l, batch, l == NLAYER-1);
    }
    mlp_all<<<NGR, FCW>>>(fc1W, fc1b, fcsW, fcsb, outW, outb, y);
}

// round 15
// speedup vs baseline: 1.0821x; 1.0821x over previous
#include <cuda_runtime.h>
#include <cuda_fp16.h>
#include <cuda_bf16.h>
#include <cuda_fp8.h>
#include <math.h>

#define NN      20000
#define NNP     20480        // padded for csr_scan vector path
#define NE      500000
#define NGR     64
#define NGAUSS  100
#define NLAYER  6
#define FCW     128
#define EMBW    92

#define DELTA     (6.0f/99.0f)
#define INV_DELTA (99.0f/6.0f)
#define COEFF     (-0.5f/(DELTA*DELTA))

// nearest-neighbor distance table: h = DELTA/256
#define MT2       25346
#define T2_INVH   4224.0f    // 99*256/6
#define T2_H      (1.0f/4224.0f)

// BN statistics subsampling
#define SUB       8
#define NSAMP     (NE/SUB)   // 62500

#define TAB_BLOCKS 100       // blocks per layer for build_tables
#define TAB_SMEM   ((NGAUSS*128 + 128)*4)
#define GEMM_BLOCKS ((NN + 63)/64)   // 313

// smem strides (halves) padded for conflict-free ldmatrix
#define A_LD  72
#define B_LD  264

// ---------------- scratch (device globals; no allocs allowed) ----------------
__device__ float  g_x[NN*64];
__device__ __nv_bfloat16 g_xh[NN*64];     // bf16 copy of x for tensor-core gemm
__device__ __half g_Ph[NN*128];           // P = x@W1, permuted, fp16
__device__ unsigned char g_Q8[NN*128];    // Q = x@W2, permuted, fp8 e4m3
__device__ unsigned char g_T8[NLAYER*MT2*128]; // tables, permuted, fp8 e4m3
__device__ int    g_deg[NNP];
__device__ int    g_rowstart[NNP+1];
__device__ int    g_cursor[NNP];
__device__ unsigned int g_pack[NE];       // src (15b) | m (<<15), CSR order
__device__ double g_bn_sum[NLAYER*128];
__device__ double g_bn_ssq[NLAYER*128];
__device__ float  g_mol[NGR*64];
__device__ float  g_cnt[NGR];

// ---------------- helpers ----------------
__device__ __forceinline__ float splusf(float x){
    float e = __expf(-fabsf(x));
    return fmaxf(x, 0.0f) + __logf(1.0f + e);
}
__device__ __forceinline__ float tanhx(float x){
    float y; asm("tanh.approx.f32 %0, %1;" : "=f"(y) : "f"(x)); return y;
}
__device__ __forceinline__ float sigmt(float x){   // sigmoid via 1 MUFU
    return fmaf(0.5f, tanhx(0.5f*x), 0.5f);
}
// channel c (0..127) -> permuted position: lane L holds {2L,2L+1,2L+64,2L+65}
__device__ __forceinline__ int chpos(int c){
    return ((c & 63) >> 1)*4 + ((c >> 6) << 1) + (c & 1);
}
__device__ __forceinline__ void ld_h4(const __half* p, float& a, float& b, float& c, float& d){
    uint2 u = *reinterpret_cast<const uint2*>(p);
    float2 f0 = __half22float2(*reinterpret_cast<__half2*>(&u.x));
    float2 f1 = __half22float2(*reinterpret_cast<__half2*>(&u.y));
    a = f0.x; b = f0.y; c = f1.x; d = f1.y;
}
// decode two fp8x4 words (Q and T), add in half2, return 4 floats
__device__ __forceinline__ void qt8_add4(unsigned uq, unsigned ut,
                                         float& a, float& b, float& c, float& d){
    __half2_raw q0 = __nv_cvt_fp8x2_to_halfraw2((__nv_fp8x2_storage_t)(uq & 0xFFFFu), __NV_E4M3);
    __half2_raw q1 = __nv_cvt_fp8x2_to_halfraw2((__nv_fp8x2_storage_t)(uq >> 16),     __NV_E4M3);
    __half2_raw t0 = __nv_cvt_fp8x2_to_halfraw2((__nv_fp8x2_storage_t)(ut & 0xFFFFu), __NV_E4M3);
    __half2_raw t1 = __nv_cvt_fp8x2_to_halfraw2((__nv_fp8x2_storage_t)(ut >> 16),     __NV_E4M3);
    __half2 s01 = __hadd2(*reinterpret_cast<__half2*>(&q0), *reinterpret_cast<__half2*>(&t0));
    __half2 s23 = __hadd2(*reinterpret_cast<__half2*>(&q1), *reinterpret_cast<__half2*>(&t1));
    float2 f0 = __half22float2(s01);
    float2 f1 = __half22float2(s23);
    a = f0.x; b = f0.y; c = f1.x; d = f1.y;
}

// ---------------- x = embedding[an] @ nuc_W + nuc_b ----------------
__global__ void nuc_kernel(const int* __restrict__ an, const float* __restrict__ emb,
                           const float* __restrict__ W, const float* __restrict__ b){
    __shared__ float Ws[EMBW*64];
    __shared__ float bs[64];
    for (int i = threadIdx.x; i < EMBW*64; i += blockDim.x) Ws[i] = W[i];
    if (threadIdx.x < 64) bs[threadIdx.x] = b[threadIdx.x];
    __syncthreads();
    int lane = threadIdx.x & 31;
    int warp = (blockIdx.x*blockDim.x + threadIdx.x) >> 5;
    int nw   = (gridDim.x*blockDim.x) >> 5;
    for (int n = warp; n < NN; n += nw){
        const float* er = emb + an[n]*EMBW;
        float a0 = bs[lane], a1 = bs[lane+32];
        #pragma unroll 4
        for (int e = 0; e < EMBW; e++){
            float v = __ldg(er + e);
            a0 = fmaf(v, Ws[e*64 + lane],      a0);
            a1 = fmaf(v, Ws[e*64 + lane + 32], a1);
        }
        g_x[n*64 + lane]       = a0;
        g_x[n*64 + lane + 32]  = a1;
        g_xh[n*64 + lane]      = __float2bfloat16(a0);
        g_xh[n*64 + lane + 32] = __float2bfloat16(a1);
    }
}

// ---------------- one-time zeroing ----------------
__global__ void csr_zero(){
    int i = blockIdx.x*blockDim.x + threadIdx.x;
    if (i < NNP) g_deg[i] = 0;
    if (i < NGR*64) g_mol[i] = 0.0f;
    if (i < NGR)    g_cnt[i] = 0.0f;
    if (i < NLAYER*128){ g_bn_sum[i] = 0.0; g_bn_ssq[i] = 0.0; }
}
__global__ void csr_hist(const int* __restrict__ nbr){
    int i = blockIdx.x*blockDim.x + threadIdx.x;
    int stride = gridDim.x*blockDim.x;
    for (int e = i; e < NE; e += stride)
        atomicAdd(&g_deg[__ldg(nbr + NE + e)], 1);
}
__global__ void csr_scan(){   // single block, 1024 threads, 20 items each (padded)
    __shared__ int wsum[32];
    int t = threadIdx.x, lane = t & 31, wid = t >> 5;
    int base = t*20;
    int4 v[5];
    int loc = 0;
    #pragma unroll
    for (int j = 0; j < 5; j++){
        v[j] = *reinterpret_cast<const int4*>(g_deg + base + j*4);
        loc += v[j].x + v[j].y + v[j].z + v[j].w;
    }
    int sc = loc;
    #pragma unroll
    for (int off = 1; off < 32; off <<= 1){
        int u = __shfl_up_sync(0xffffffffu, sc, off);
        if (lane >= off) sc += u;
    }
    if (lane == 31) wsum[wid] = sc;
    __syncthreads();
    if (wid == 0){
        int w = wsum[lane];
        #pragma unroll
        for (int off = 1; off < 32; off <<= 1){
            int u = __shfl_up_sync(0xffffffffu, w, off);
            if (lane >= off) w += u;
        }
        wsum[lane] = w;
    }
    __syncthreads();
    int run = sc - loc + (wid ? wsum[wid-1] : 0);
    #pragma unroll
    for (int j = 0; j < 5; j++){
        int4 rs;
        rs.x = run; run += v[j].x;
        rs.y = run; run += v[j].y;
        rs.z = run; run += v[j].z;
        rs.w = run; run += v[j].w;
        *reinterpret_cast<int4*>(g_rowstart + base + j*4) = rs;
        *reinterpret_cast<int4*>(g_cursor   + base + j*4) = rs;
    }
    if (t == 1023) g_rowstart[NNP] = wsum[31];
}
__global__ void csr_scatter(const int* __restrict__ nbr, const float* __restrict__ dist){
    int i = blockIdx.x*blockDim.x + threadIdx.x;
    int stride = gridDim.x*blockDim.x;
    for (int e = i; e < NE; e += stride){
        int dn = __ldg(nbr + NE + e);
        int sn = __ldg(nbr + e);
        float d = __ldg(dist + e);
        int m = min(__float2int_rn(d * T2_INVH), MT2 - 1);
        int pos = atomicAdd(&g_cursor[dn], 1);
        g_pack[pos] = (unsigned)sn | ((unsigned)m << 15);
    }
}

// ---- build ALL 6 tables up front, warp-autonomous (fp8 output) ----
__global__ void build_tables(const float* __restrict__ convW, const float* __restrict__ convb){
    extern __shared__ float sm[];
    float* W3s = sm;                 // [100][128]
    float* bs  = sm + NGAUSS*128;    // [128]
    int layer = blockIdx.x / TAB_BLOCKS;
    int tb    = blockIdx.x % TAB_BLOCKS;
    const float* W3 = convW + layer*228*128 + 128*128;
    const float* bl = convb + layer*128;
    unsigned char* Tl = g_T8 + (size_t)layer*MT2*128;
    for (int i = threadIdx.x; i < NGAUSS*128; i += blockDim.x) W3s[i] = W3[i];
    if (threadIdx.x < 128) bs[threadIdx.x] = bl[threadIdx.x];
    __syncthreads();
    int lane = threadIdx.x & 31;
    int wid  = threadIdx.x >> 5;     // 8 warps per block
    int c0 = lane*4;                 // this lane's 4 channels
    int p0 = chpos(c0), p1 = chpos(c0+1), p2 = chpos(c0+2), p3 = chpos(c0+3);
    float b0 = bs[c0], b1 = bs[c0+1], b2 = bs[c0+2], b3 = bs[c0+3];
    int per = (MT2 + TAB_BLOCKS - 1) / TAB_BLOCKS;
    int m0 = tb*per;
    int m1 = min(m0 + per, MT2);
    for (int m = m0 + wid; m < m1; m += 8){
        float d = (float)m * T2_H;
        int kc = __float2int_rn(d * INV_DELTA);
        int k0 = max(kc - 8, 0);
        int k1 = min(kc + 8, NGAUSS - 1);
        int cnt = k1 - k0 + 1;
        float myw = 0.0f;
        if (lane < cnt){ float t = d - (float)(k0+lane)*DELTA; myw = __expf(COEFF*t*t); }
        float a0 = b0, a1 = b1, a2 = b2, a3 = b3;
        for (int k = 0; k < cnt; k++){
            float w = __shfl_sync(0xffffffffu, myw, k);
            float4 wr = *reinterpret_cast<const float4*>(W3s + (k0+k)*128 + c0);
            a0 = fmaf(w, wr.x, a0);
            a1 = fmaf(w, wr.y, a1);
            a2 = fmaf(w, wr.z, a2);
            a3 = fmaf(w, wr.w, a3);
        }
        unsigned char* out = Tl + (size_t)m*128;
        out[p0] = (unsigned char)__nv_cvt_float_to_fp8(a0, __NV_SATFINITE, __NV_E4M3);
        out[p1] = (unsigned char)__nv_cvt_float_to_fp8(a1, __NV_SATFINITE, __NV_E4M3);
        out[p2] = (unsigned char)__nv_cvt_float_to_fp8(a2, __NV_SATFINITE, __NV_E4M3);
        out[p3] = (unsigned char)__nv_cvt_float_to_fp8(a3, __NV_SATFINITE, __NV_E4M3);
    }
}

// ---------------- P/Q gemm via tensor cores (mma.sync bf16, fp32 accum) --------
// cols 0..127 -> P (fp16), 128..255 -> Q (fp8), both permuted
__global__ void gemm_mma(const float* __restrict__ Wl){
    __shared__ __nv_bfloat16 As[64*A_LD];
    __shared__ __nv_bfloat16 Bs[64*B_LD];
    int tid = threadIdx.x;
    int n0 = blockIdx.x * 64;
    for (int i = tid; i < 64*256; i += 256){
        int k = i >> 8, n = i & 255;
        float w = (n < 128) ? __ldg(Wl + k*128 + n) : __ldg(Wl + (64+k)*128 + (n-128));
        Bs[k*B_LD + n] = __float2bfloat16(w);
    }
    for (int i = tid; i < 64*64; i += 256){
        int r = i >> 6, k = i & 63;
        int node = n0 + r;
        As[r*A_LD + k] = (node < NN) ? g_xh[node*64 + k] : __float2bfloat16(0.0f);
    }
    __syncthreads();
    int lane = tid & 31, wid = tid >> 5;
    int wm = (wid >> 2) * 32;
    int wn = (wid & 3) * 64;
    float acc[2][8][4];
    #pragma unroll
    for (int mt = 0; mt < 2; mt++)
        #pragma unroll
        for (int nt = 0; nt < 8; nt++)
            #pragma unroll
            for (int q = 0; q < 4; q++) acc[mt][nt][q] = 0.0f;

    int ar = lane & 15;
    int ac = (lane >> 4) * 8;
    int bk = lane & 7;
    int bh = (lane >> 3) & 1;
    #pragma unroll
    for (int ks = 0; ks < 4; ks++){
        unsigned a[2][4];
        #pragma unroll
        for (int mt = 0; mt < 2; mt++){
            unsigned sa = (unsigned)__cvta_generic_to_shared(
                As + (wm + mt*16 + ar)*A_LD + ks*16 + ac);
            asm volatile("ldmatrix.sync.aligned.m8n8.x4.shared.b16 {%0,%1,%2,%3}, [%4];"
                : "=r"(a[mt][0]), "=r"(a[mt][1]), "=r"(a[mt][2]), "=r"(a[mt][3]) : "r"(sa));
        }
        unsigned b[8][2];
        #pragma unroll
        for (int nt = 0; nt < 8; nt++){
            unsigned sb = (unsigned)__cvta_generic_to_shared(
                Bs + (ks*16 + bh*8 + bk)*B_LD + wn + nt*8);
            asm volatile("ldmatrix.sync.aligned.m8n8.x2.trans.shared.b16 {%0,%1}, [%2];"
                : "=r"(b[nt][0]), "=r"(b[nt][1]) : "r"(sb));
        }
        #pragma unroll
        for (int mt = 0; mt < 2; mt++)
            #pragma unroll
            for (int nt = 0; nt < 8; nt++){
                asm volatile(
                    "mma.sync.aligned.m16n8k16.row.col.f32.bf16.bf16.f32 "
                    "{%0,%1,%2,%3}, {%4,%5,%6,%7}, {%8,%9}, {%0,%1,%2,%3};"
                    : "+f"(acc[mt][nt][0]), "+f"(acc[mt][nt][1]),
                      "+f"(acc[mt][nt][2]), "+f"(acc[mt][nt][3])
                    : "r"(a[mt][0]), "r"(a[mt][1]), "r"(a[mt][2]), "r"(a[mt][3]),
                      "r"(b[nt][0]), "r"(b[nt][1]));
            }
    }
    #pragma unroll
    for (int mt = 0; mt < 2; mt++)
        #pragma unroll
        for (int nt = 0; nt < 8; nt++){
            int col = wn + nt*8 + (lane & 3)*2;
            int r0 = n0 + wm + mt*16 + (lane >> 2);
            int r1 = r0 + 8;
            if (col < 128){
                int cp = chpos(col);
                if (r0 < NN){
                    g_Ph[r0*128 + cp]     = __float2half_rn(acc[mt][nt][0]);
                    g_Ph[r0*128 + cp + 1] = __float2half_rn(acc[mt][nt][1]);
                }
                if (r1 < NN){
                    g_Ph[r1*128 + cp]     = __float2half_rn(acc[mt][nt][2]);
                    g_Ph[r1*128 + cp + 1] = __float2half_rn(acc[mt][nt][3]);
                }
            } else {
                int cp = chpos(col - 128);
                if (r0 < NN){
                    g_Q8[r0*128 + cp]     = (unsigned char)__nv_cvt_float_to_fp8(acc[mt][nt][0], __NV_SATFINITE, __NV_E4M3);
                    g_Q8[r0*128 + cp + 1] = (unsigned char)__nv_cvt_float_to_fp8(acc[mt][nt][1], __NV_SATFINITE, __NV_E4M3);
                }
                if (r1 < NN){
                    g_Q8[r1*128 + cp]     = (unsigned char)__nv_cvt_float_to_fp8(acc[mt][nt][2], __NV_SATFINITE, __NV_E4M3);
                    g_Q8[r1*128 + cp + 1] = (unsigned char)__nv_cvt_float_to_fp8(acc[mt][nt][3], __NV_SATFINITE, __NV_E4M3);
                }
            }
        }
}

// ---- BN stats over every SUB-th edge, edge-centric flat loop ----
__global__ void bn_pass(const int* __restrict__ nbr, const float* __restrict__ dist, int layer){
    __shared__ float s_sum[128];
    __shared__ float s_ssq[128];
    if (threadIdx.x < 128){ s_sum[threadIdx.x] = 0.0f; s_ssq[threadIdx.x] = 0.0f; }
    __syncthreads();
    const unsigned char* Tl = g_T8 + (size_t)layer*MT2*128;
    int lane = threadIdx.x & 31;
    int warp = (blockIdx.x*blockDim.x + threadIdx.x) >> 5;
    int nw   = (gridDim.x*blockDim.x) >> 5;
    float s0=0,s1=0,s2=0,s3=0, q0=0,q1=0,q2=0,q3=0;
    for (int s = warp; s < NSAMP; s += nw){
        int e = s * SUB;
        int dn = __ldg(nbr + NE + e);
        int sn = __ldg(nbr + e);
        float d = __ldg(dist + e);
        int m = min(__float2int_rn(d * T2_INVH), MT2 - 1);
        float p0,p1,p2,p3, a0,a1,a2,a3;
        ld_h4(g_Ph + dn*128 + lane*4, p0,p1,p2,p3);
        unsigned uq = __ldg(reinterpret_cast<const unsigned*>(g_Q8 + sn*128) + lane);
        unsigned ut = __ldg(reinterpret_cast<const unsigned*>(Tl + (size_t)m*128) + lane);
        qt8_add4(uq, ut, a0,a1,a2,a3);
        float z0 = p0+a0, z1 = p1+a1, z2 = p2+a2, z3 = p3+a3;
        s0 += z0; s1 += z1; s2 += z2; s3 += z3;
        q0 = fmaf(z0,z0,q0); q1 = fmaf(z1,z1,q1);
        q2 = fmaf(z2,z2,q2); q3 = fmaf(z3,z3,q3);
    }
    int c = lane*4;   // pos-space
    atomicAdd(&s_sum[c+0],s0); atomicAdd(&s_sum[c+1],s1); atomicAdd(&s_sum[c+2],s2); atomicAdd(&s_sum[c+3],s3);
    atomicAdd(&s_ssq[c+0],q0); atomicAdd(&s_ssq[c+1],q1); atomicAdd(&s_ssq[c+2],q2); atomicAdd(&s_ssq[c+3],q3);
    __syncthreads();
    if (threadIdx.x < 128){
        atomicAdd(&g_bn_sum[layer*128 + threadIdx.x], (double)s_sum[threadIdx.x]);
        atomicAdd(&g_bn_ssq[layer*128 + threadIdx.x], (double)s_ssq[threadIdx.x]);
    }
}

// ---- pass2 (warp per node): BN finalize inline, recompute z, act, agg, LN, residual ----
__global__ void edge_pass2(const float* __restrict__ lng, const float* __restrict__ lnb,
                           const float* __restrict__ bg,  const float* __restrict__ bb,
                           int layer, const int* __restrict__ batch, int do_pool){
    __shared__ __align__(16) float s_ss[256];    // scale[128] | shift[128] (pos-space)
    {
        int t = threadIdx.x;
        if (t < 128){
            int c = 2*(t >> 2) + (t & 1) + (((t >> 1) & 1) << 6);   // inverse perm
            double mu  = g_bn_sum[layer*128 + t] * (1.0/NSAMP);
            double var = g_bn_ssq[layer*128 + t] * (1.0/NSAMP) - mu*mu;
            double inv = 1.0 / sqrt(var + 1e-5);
            double sc  = (double)__ldg(bg + c) * inv;
            s_ss[t]       = (float)sc;
            s_ss[128 + t] = (float)((double)__ldg(bb + c) - mu*sc);
        }
    }
    __syncthreads();
    const unsigned char* Tl = g_T8 + (size_t)layer*MT2*128;
    int lane = threadIdx.x & 31;
    int warp = (blockIdx.x*blockDim.x + threadIdx.x) >> 5;
    int nw   = (gridDim.x*blockDim.x) >> 5;
    float4 sc = *reinterpret_cast<const float4*>(s_ss + lane*4);
    float4 sh = *reinterpret_cast<const float4*>(s_ss + 128 + lane*4);
    float2 lg = *reinterpret_cast<const float2*>(lng + 2*lane);
    float2 lb = *reinterpret_cast<const float2*>(lnb + 2*lane);
    for (int n = warp; n < NN; n += nw){
        int i0 = g_rowstart[n], i1 = g_rowstart[n+1];
        float p0,p1,p2,p3;
        ld_h4(g_Ph + n*128 + lane*4, p0,p1,p2,p3);
        float ph0 = fmaf(p0, sc.x, sh.x);
        float ph1 = fmaf(p1, sc.y, sh.y);
        float ph2 = fmaf(p2, sc.z, sh.z);
        float ph3 = fmaf(p3, sc.w, sh.w);
        float a0 = 0.0f, a1 = 0.0f;
        for (int base = i0; base < i1; base += 32){
            int cnt = min(32, i1 - base);
            unsigned myv = 0;
            if (base + lane < i1) myv = __ldg(&g_pack[base + lane]);
            int e = 0;
            for (; e + 2 <= cnt; e += 2){
                unsigned va = __shfl_sync(0xffffffffu, myv, e);
                unsigned vb = __shfl_sync(0xffffffffu, myv, e+1);
                unsigned uqa = __ldg(reinterpret_cast<const unsigned*>(g_Q8 + (va & 0x7FFFu)*128) + lane);
                unsigned uta = __ldg(reinterpret_cast<const unsigned*>(Tl + (size_t)(va >> 15)*128) + lane);
                unsigned uqb = __ldg(reinterpret_cast<const unsigned*>(g_Q8 + (vb & 0x7FFFu)*128) + lane);
                unsigned utb = __ldg(reinterpret_cast<const unsigned*>(Tl + (size_t)(vb >> 15)*128) + lane);
                float A0,A1,A2,A3, B0,B1,B2,B3;
                qt8_add4(uqa, uta, A0,A1,A2,A3);
                qt8_add4(uqb, utb, B0,B1,B2,B3);
                {
                    float z0 = fmaf(A0, sc.x, ph0);
                    float z1 = fmaf(A1, sc.y, ph1);
                    float z2 = fmaf(A2, sc.z, ph2);
                    float z3 = fmaf(A3, sc.w, ph3);
                    a0 = fmaf(sigmt(z0), splusf(z2), a0);
                    a1 = fmaf(sigmt(z1), splusf(z3), a1);
                }
                {
                    float z0 = fmaf(B0, sc.x, ph0);
                    float z1 = fmaf(B1, sc.y, ph1);
                    float z2 = fmaf(B2, sc.z, ph2);
                    float z3 = fmaf(B3, sc.w, ph3);
                    a0 = fmaf(sigmt(z0), splusf(z2), a0);
                    a1 = fmaf(sigmt(z1), splusf(z3), a1);
                }
            }
            if (e < cnt){
                unsigned va = __shfl_sync(0xffffffffu, myv, e);
                unsigned uqa = __ldg(reinterpret_cast<const unsigned*>(g_Q8 + (va & 0x7FFFu)*128) + lane);
                unsigned uta = __ldg(reinterpret_cast<const unsigned*>(Tl + (size_t)(va >> 15)*128) + lane);
                float A0,A1,A2,A3;
                qt8_add4(uqa, uta, A0,A1,A2,A3);
                float z0 = fmaf(A0, sc.x, ph0);
                float z1 = fmaf(A1, sc.y, ph1);
                float z2 = fmaf(A2, sc.z, ph2);
                float z3 = fmaf(A3, sc.w, ph3);
                a0 = fmaf(sigmt(z0), splusf(z2), a0);
                a1 = fmaf(sigmt(z1), splusf(z3), a1);
            }
        }
        // LayerNorm over 64 channels (2 per lane: ch 2L, 2L+1)
        float s = a0 + a1;
        #pragma unroll
        for (int o = 16; o > 0; o >>= 1) s += __shfl_xor_sync(0xffffffffu, s, o);
        float mu = s * (1.0f/64.0f);
        float d0 = a0 - mu, d1 = a1 - mu;
        float vv = d0*d0 + d1*d1;
        #pragma unroll
        for (int o = 16; o > 0; o >>= 1) vv += __shfl_xor_sync(0xffffffffu, vv, o);
        float inv = rsqrtf(vv * (1.0f/64.0f) + 1e-5f);
        float2 x = *reinterpret_cast<const float2*>(g_x + n*64 + 2*lane);
        float h0 = fmaf(d0*inv, lg.x, lb.x) + x.x;
        float h1 = fmaf(d1*inv, lg.y, lb.y) + x.y;
        float xr0 = splusf(h0), xr1 = splusf(h1);
        if (do_pool){
            int g = __ldg(batch + n);
            atomicAdd(&g_mol[g*64 + 2*lane],     xr0);
            atomicAdd(&g_mol[g*64 + 2*lane + 1], xr1);
            if (lane == 0) atomicAdd(&g_cnt[g], 1.0f);
        } else {
            *reinterpret_cast<float2*>(g_x + n*64 + 2*lane) = make_float2(xr0, xr1);
            g_xh[n*64 + 2*lane]     = __float2bfloat16(xr0);
            g_xh[n*64 + 2*lane + 1] = __float2bfloat16(xr1);
        }
    }
}

// ---------------- fused MLP head ----------------
__global__ void mlp_all(const float* __restrict__ fc1W, const float* __restrict__ fc1b,
                        const float* __restrict__ fcsW, const float* __restrict__ fcsb,
                        const float* __restrict__ outW, const float* __restrict__ outb,
                        float* __restrict__ out){
    __shared__ float buf[2][FCW];
    __shared__ float red[FCW];
    int g = blockIdx.x, j = threadIdx.x;   // 128 threads
    if (j < 64){
        float c = fmaxf(g_cnt[g], 1.0f);
        buf[0][j] = g_mol[g*64 + j] / c;
    }
    __syncthreads();
    float acc = fc1b[j];
    #pragma unroll 4
    for (int f = 0; f < 64; f++) acc = fmaf(buf[0][f], __ldg(fc1W + f*FCW + j), acc);
    buf[1][j] = splusf(acc);
    __syncthreads();
    int cur = 1;
    for (int l = 0; l < 3; l++){
        const float* W = fcsW + l*FCW*FCW;
        float a = fcsb[l*FCW + j];
        #pragma unroll 4
        for (int f = 0; f < FCW; f++) a = fmaf(buf[cur][f], __ldg(W + f*FCW + j), a);
        buf[cur ^ 1][j] = splusf(a);
        cur ^= 1;
        __syncthreads();
    }
    red[j] = buf[cur][j] * __ldg(outW + j);
    __syncthreads();
    for (int o = 64; o > 0; o >>= 1){
        if (j < o) red[j] += red[j + o];
        __syncthreads();
    }
    if (j == 0) out[g] = red[0] + outb[0];
}

// ---------------- launch ----------------
extern "C" void kernel_launch(void* const* d_in, const int* in_sizes, int n_in,
                              void* d_out, int out_size){
    const int*   an    = (const int*)  d_in[0];
    const int*   nbr   = (const int*)  d_in[1];
    const float* dist  = (const float*)d_in[2];
    const int*   batch = (const int*)  d_in[3];
    const float* emb   = (const float*)d_in[4];
    const float* nucW  = (const float*)d_in[5];
    const float* nucb  = (const float*)d_in[6];
    const float* convW = (const float*)d_in[7];
    const float* convb = (const float*)d_in[8];
    const float* bng   = (const float*)d_in[9];
    const float* bnb   = (const float*)d_in[10];
    const float* lng   = (const float*)d_in[11];
    const float* lnb   = (const float*)d_in[12];
    const float* fc1W  = (const float*)d_in[13];
    const float* fc1b  = (const float*)d_in[14];
    const float* fcsW  = (const float*)d_in[15];
    const float* fcsb  = (const float*)d_in[16];
    const float* outW  = (const float*)d_in[17];
    const float* outb  = (const float*)d_in[18];
    float* y = (float*)d_out;

    static cudaStream_t sA = 0, sB = 0;
    static cudaEvent_t  evR = 0, evA = 0, evB = 0;
    if (sA == 0){
        cudaStreamCreateWithFlags(&sA, cudaStreamNonBlocking);
        cudaStreamCreateWithFlags(&sB, cudaStreamNonBlocking);
        cudaEventCreateWithFlags(&evR, cudaEventDisableTiming);
        cudaEventCreateWithFlags(&evA, cudaEventDisableTiming);
        cudaEventCreateWithFlags(&evB, cudaEventDisableTiming);
    }

    cudaFuncSetAttribute(build_tables, cudaFuncAttributeMaxDynamicSharedMemorySize, TAB_SMEM);

    // ---- forked setup: tables (sA) || nuc (sB) || csr chain (legacy) ----
    cudaEventRecord(evR, 0);
    cudaStreamWaitEvent(sA, evR, 0);
    cudaStreamWaitEvent(sB, evR, 0);

    build_tables<<<NLAYER*TAB_BLOCKS, 256, TAB_SMEM, sA>>>(convW, convb);
    nuc_kernel<<<640, 256, 0, sB>>>(an, emb, nucW, nucb);

    csr_zero<<<80, 256>>>();
    csr_hist<<<640, 256>>>(nbr);
    csr_scan<<<1, 1024>>>();
    csr_scatter<<<640, 256>>>(nbr, dist);

    cudaEventRecord(evA, sA);
    cudaEventRecord(evB, sB);
    cudaStreamWaitEvent(0, evA, 0);
    cudaStreamWaitEvent(0, evB, 0);

    // ---- per-layer pipeline (legacy stream, serial by dependency) ----
    for (int l = 0; l < NLAYER; l++){
        gemm_mma<<<GEMM_BLOCKS, 256>>>(convW + l*228*128);
        bn_pass<<<592, 256>>>(nbr, dist, l);
        edge_pass2<<<640, 256>>>(lng + l*64, lnb + l*64, bng + l*128, bnb + l*128,
                                 l, batch, l == NLAYER-1);
    }
    mlp_all<<<NGR, FCW>>>(fc1W, fc1b, fcsW, fcsb, outW, outb, y);
}